// round 8
// baseline (speedup 1.0000x reference)
#include <cuda_runtime.h>
#include <math.h>

#define NVOX 65536            // 64*64*16 voxels
#define CCH 64
#define NHEAD 8
#define DHEAD 8

typedef unsigned long long u64;

// ---------------- scratch (device globals; no allocation allowed) ----------
__device__ float f_xu[CCH * NVOX];   // upsampled x, channel-first [c][v]
__device__ float f_q[NVOX * CCH];    // q projection, voxel-major [v][c]
__device__ float f_k[NVOX * CCH];
__device__ float f_v[NVOX * CCH];
__device__ float f_o[CCH * NVOX];    // attention output, channel-first [c][v]
__device__ float g_psum[512], g_psumsq[512];   // [0:256] xu quarters, [256:512] skip quarters
__device__ float g_Wf[3][CCH * CCH];           // folded Wq, Wk, Wv
__device__ float g_bf[3][CCH];

// ---------------- helpers ---------------------------------------------------
__device__ __forceinline__ u64 ffma2(u64 a, u64 b, u64 c) {
    u64 d;
    asm("fma.rn.f32x2 %0, %1, %2, %3;" : "=l"(d) : "l"(a), "l"(b), "l"(c));
    return d;
}
__device__ __forceinline__ u64 fmul2(u64 a, u64 b) {
    u64 d;
    asm("mul.rn.f32x2 %0, %1, %2;" : "=l"(d) : "l"(a), "l"(b));
    return d;
}
__device__ __forceinline__ u64 packdup(float w) {
    unsigned u = __float_as_uint(w);
    return ((u64)u << 32) | (u64)u;
}
__device__ __forceinline__ float f2lo(u64 a) { return __uint_as_float((unsigned)a); }
__device__ __forceinline__ float f2hi(u64 a) { return __uint_as_float((unsigned)(a >> 32)); }

// ---------------- 1) trilinear upsample x(64,32,32,8) -> f_xu(64,64,64,16) --
__global__ __launch_bounds__(256) void upsample_kernel(const float* __restrict__ x) {
    int v = blockIdx.x * 256 + threadIdx.x;
    int h = v >> 10;
    int w = (v >> 4) & 63;
    int z = v & 15;

    const float rh = (float)(31.0 / 63.0);
    const float rw = (float)(31.0 / 63.0);
    const float rz = (float)(7.0 / 15.0);

    float ph = (float)h * rh; int ih = (int)ph; if (ih > 30) ih = 30; float fh = ph - (float)ih;
    float pw = (float)w * rw; int iw = (int)pw; if (iw > 30) iw = 30; float fw = pw - (float)iw;
    float pz = (float)z * rz; int iz = (int)pz; if (iz > 6)  iz = 6;  float fz = pz - (float)iz;

    int base = ih * 256 + iw * 8 + iz;   // strides: h=256, w=8, z=1
    int cbase = blockIdx.y * 8;

#pragma unroll
    for (int ci = 0; ci < 8; ci++) {
        int c = cbase + ci;
        const float* xc = x + c * 8192 + base;
        float c000 = xc[0],   c100 = xc[256], c010 = xc[8],   c110 = xc[264];
        float c001 = xc[1],   c101 = xc[257], c011 = xc[9],   c111 = xc[265];
        float a00 = c000 + fh * (c100 - c000);
        float a10 = c010 + fh * (c110 - c010);
        float a01 = c001 + fh * (c101 - c001);
        float a11 = c011 + fh * (c111 - c011);
        float b0  = a00 + fw * (a10 - a00);
        float b1  = a01 + fw * (a11 - a01);
        f_xu[c * NVOX + v] = b0 + fz * (b1 - b0);
    }
}

// ---------------- 2) per-channel partial sum / sumsq (xu and skip) ----------
__global__ __launch_bounds__(256) void stats_kernel(const float* __restrict__ skip) {
    int b = blockIdx.x;   // 0..511
    const int quart = NVOX / 4;
    const float* p;
    if (b < 256) p = f_xu + (b >> 2) * NVOX + (b & 3) * quart;
    else         p = skip + ((b - 256) >> 2) * NVOX + (b & 3) * quart;

    const float4* p4 = (const float4*)p;
    float s = 0.f, s2 = 0.f;
    for (int i = threadIdx.x; i < quart / 4; i += 256) {
        float4 val = p4[i];
        s  += val.x + val.y + val.z + val.w;
        s2 += val.x * val.x + val.y * val.y + val.z * val.z + val.w * val.w;
    }
    __shared__ float sh1[256], sh2[256];
    sh1[threadIdx.x] = s; sh2[threadIdx.x] = s2;
    __syncthreads();
    for (int off = 128; off > 0; off >>= 1) {
        if (threadIdx.x < off) {
            sh1[threadIdx.x] += sh1[threadIdx.x + off];
            sh2[threadIdx.x] += sh2[threadIdx.x + off];
        }
        __syncthreads();
    }
    if (threadIdx.x == 0) { g_psum[b] = sh1[0]; g_psumsq[b] = sh2[0]; }
}

// ---------------- 3) fold instance-norm (+ q scale) into weights -----------
__global__ void fold_kernel(const float* __restrict__ Wq, const float* __restrict__ bq,
                            const float* __restrict__ Wk, const float* __restrict__ bk,
                            const float* __restrict__ Wv, const float* __restrict__ bv) {
    __shared__ float skv[64], okv[64], sq_[64], oq_[64];
    int t = threadIdx.x;    // 64 threads
    const float invN = 1.0f / 65536.0f;
    float m  = (g_psum[4 * t] + g_psum[4 * t + 1] + g_psum[4 * t + 2] + g_psum[4 * t + 3]) * invN;
    float va = (g_psumsq[4 * t] + g_psumsq[4 * t + 1] + g_psumsq[4 * t + 2] + g_psumsq[4 * t + 3]) * invN - m * m;
    float sc = rsqrtf(va + 1e-5f);
    skv[t] = sc; okv[t] = -m * sc;
    m  = (g_psum[256 + 4 * t] + g_psum[257 + 4 * t] + g_psum[258 + 4 * t] + g_psum[259 + 4 * t]) * invN;
    va = (g_psumsq[256 + 4 * t] + g_psumsq[257 + 4 * t] + g_psumsq[258 + 4 * t] + g_psumsq[259 + 4 * t]) * invN - m * m;
    sc = rsqrtf(va + 1e-5f);
    sq_[t] = sc; oq_[t] = -m * sc;
    __syncthreads();

    const float scale = 0.3535533905932738f;  // dh^-0.5, dh=8
    float aq = 0.f, ak = 0.f, av = 0.f;
    for (int c = 0; c < 64; c++) {
        float wq = Wq[c * 64 + t]; g_Wf[0][c * 64 + t] = wq * sq_[c] * scale; aq += oq_[c] * wq;
        float wk = Wk[c * 64 + t]; g_Wf[1][c * 64 + t] = wk * skv[c];          ak += okv[c] * wk;
        float wv = Wv[c * 64 + t]; g_Wf[2][c * 64 + t] = wv * skv[c];          av += okv[c] * wv;
    }
    g_bf[0][t] = scale * (bq[t] + aq);
    g_bf[1][t] = bk[t] + ak;
    g_bf[2][t] = bv[t] + av;
}

// ---------------- 4) generic projection (software-pipelined) ----------------
// Block: 128 thr, 64 voxels. og=tid>>4 (8 output groups of 8 ch), vg=tid&15
// (4 voxels each). Explicit register double-buffer over the c-loop hides the
// ~29cyc LDS latency behind 32 issue-cycles of FFMA2 per iteration.
template <bool CF_OUT>
__global__ __launch_bounds__(128) void proj_kernel(int sel,
        const float* __restrict__ skip,
        const float* __restrict__ Wext, const float* __restrict__ bext,
        float* __restrict__ outext) {
    __shared__ float s_in[64 * 64];   // [c][vox]  16KB
    __shared__ u64  sW[64 * 32];      // [c][outpair] 16KB
    __shared__ u64  sB[32];

    const float* W  = (sel < 3) ? g_Wf[sel] : Wext;
    const float* bb = (sel < 3) ? g_bf[sel] : bext;
    const float* in = (sel == 0) ? skip : ((sel == 3) ? f_o : f_xu);
    float* out = (sel == 0) ? f_q : ((sel == 1) ? f_k : ((sel == 2) ? f_v : outext));

    int tid = threadIdx.x;
    int vb  = blockIdx.x * 64;

    const u64* Wu = (const u64*)W;
    for (int i = tid; i < 2048; i += 128) sW[i] = Wu[i];
    if (tid < 32) sB[tid] = ((const u64*)bb)[tid];
    for (int i = tid; i < 1024; i += 128) {
        int row = i >> 4, col = (i & 15) << 2;
        *(float4*)&s_in[row * 64 + col] = *(const float4*)(in + (size_t)row * NVOX + vb + col);
    }
    __syncthreads();

    int og = tid >> 4;     // 0..7
    int vg = tid & 15;     // 0..15
    const float* pin = &s_in[vg * 4];
    const u64*  pw  = &sW[og * 4];

    u64 acc[4][4];
#pragma unroll
    for (int v = 0; v < 4; v++)
#pragma unroll
        for (int op = 0; op < 4; op++) acc[v][op] = sB[og * 4 + op];

    // double-buffered pipeline: buffers A (even c) and B (odd c)
    float4 ivA = *(const float4*)(pin);
    ulonglong2 waA = *(const ulonglong2*)(pw);
    ulonglong2 wbA = *(const ulonglong2*)(pw + 2);
    float4 ivB; ulonglong2 waB, wbB;

#pragma unroll 4
    for (int c = 0; c < 64; c += 2) {
        // prefetch c+1
        ivB = *(const float4*)(pin + (c + 1) * 64);
        waB = *(const ulonglong2*)(pw + (c + 1) * 32);
        wbB = *(const ulonglong2*)(pw + (c + 1) * 32 + 2);
        // compute c (buffer A)
        {
            u64 i0 = packdup(ivA.x), i1 = packdup(ivA.y), i2 = packdup(ivA.z), i3 = packdup(ivA.w);
            u64 w0 = waA.x, w1 = waA.y, w2 = wbA.x, w3 = wbA.y;
            acc[0][0] = ffma2(i0, w0, acc[0][0]); acc[0][1] = ffma2(i0, w1, acc[0][1]);
            acc[0][2] = ffma2(i0, w2, acc[0][2]); acc[0][3] = ffma2(i0, w3, acc[0][3]);
            acc[1][0] = ffma2(i1, w0, acc[1][0]); acc[1][1] = ffma2(i1, w1, acc[1][1]);
            acc[1][2] = ffma2(i1, w2, acc[1][2]); acc[1][3] = ffma2(i1, w3, acc[1][3]);
            acc[2][0] = ffma2(i2, w0, acc[2][0]); acc[2][1] = ffma2(i2, w1, acc[2][1]);
            acc[2][2] = ffma2(i2, w2, acc[2][2]); acc[2][3] = ffma2(i2, w3, acc[2][3]);
            acc[3][0] = ffma2(i3, w0, acc[3][0]); acc[3][1] = ffma2(i3, w1, acc[3][1]);
            acc[3][2] = ffma2(i3, w2, acc[3][2]); acc[3][3] = ffma2(i3, w3, acc[3][3]);
        }
        // prefetch c+2 (wraps harmlessly to 0 on last iteration)
        int cn = (c + 2) & 63;
        ivA = *(const float4*)(pin + cn * 64);
        waA = *(const ulonglong2*)(pw + cn * 32);
        wbA = *(const ulonglong2*)(pw + cn * 32 + 2);
        // compute c+1 (buffer B)
        {
            u64 i0 = packdup(ivB.x), i1 = packdup(ivB.y), i2 = packdup(ivB.z), i3 = packdup(ivB.w);
            u64 w0 = waB.x, w1 = waB.y, w2 = wbB.x, w3 = wbB.y;
            acc[0][0] = ffma2(i0, w0, acc[0][0]); acc[0][1] = ffma2(i0, w1, acc[0][1]);
            acc[0][2] = ffma2(i0, w2, acc[0][2]); acc[0][3] = ffma2(i0, w3, acc[0][3]);
            acc[1][0] = ffma2(i1, w0, acc[1][0]); acc[1][1] = ffma2(i1, w1, acc[1][1]);
            acc[1][2] = ffma2(i1, w2, acc[1][2]); acc[1][3] = ffma2(i1, w3, acc[1][3]);
            acc[2][0] = ffma2(i2, w0, acc[2][0]); acc[2][1] = ffma2(i2, w1, acc[2][1]);
            acc[2][2] = ffma2(i2, w2, acc[2][2]); acc[2][3] = ffma2(i2, w3, acc[2][3]);
            acc[3][0] = ffma2(i3, w0, acc[3][0]); acc[3][1] = ffma2(i3, w1, acc[3][1]);
            acc[3][2] = ffma2(i3, w2, acc[3][2]); acc[3][3] = ffma2(i3, w3, acc[3][3]);
        }
    }

    if (!CF_OUT) {
#pragma unroll
        for (int v = 0; v < 4; v++) {
            size_t base = (size_t)(vb + vg * 4 + v) * 64 + og * 8;
            ulonglong2 p0; p0.x = acc[v][0]; p0.y = acc[v][1];
            ulonglong2 p1; p1.x = acc[v][2]; p1.y = acc[v][3];
            *(ulonglong2*)(out + base)     = p0;
            *(ulonglong2*)(out + base + 4) = p1;
        }
    } else {
#pragma unroll
        for (int op = 0; op < 4; op++) {
            int ch = og * 8 + 2 * op;
            float4 lo = make_float4(f2lo(acc[0][op]), f2lo(acc[1][op]), f2lo(acc[2][op]), f2lo(acc[3][op]));
            float4 hi = make_float4(f2hi(acc[0][op]), f2hi(acc[1][op]), f2hi(acc[2][op]), f2hi(acc[3][op]));
            *(float4*)(out + (size_t)ch * NVOX + vb + vg * 4)       = lo;
            *(float4*)(out + (size_t)(ch + 1) * NVOX + vb + vg * 4) = hi;
        }
    }
}

// ---------------- 5) tiled neighborhood attention (f32x2 packed) ------------
__device__ __forceinline__ int sidx(int hl, int j) {
    return (hl * 2 + j) ^ (((hl >> 2) & 3) << 1);
}

__global__ __launch_bounds__(256) void attn_kernel(const float* __restrict__ rpb) {
    __shared__ float4 ks4[1216];
    __shared__ float4 vs4[1216];
    __shared__ float bias_s[125];

    int tid  = threadIdx.x;
    int tb   = blockIdx.x;          // 0..255 : 8x8x4 tiles
    int head = blockIdx.y;
    int h0 = (tb >> 5) * 8;
    int w0 = ((tb >> 2) & 7) * 8;
    int z0 = (tb & 3) * 4;

    for (int i = tid; i < 600; i += 256) {
        int ah = i / 60; int r = i - ah * 60; int aw = r / 6; int az = r - aw * 6;
        int gh = min(max(h0 - 1 + ah, 0), 63);
        int gw = min(max(w0 - 1 + aw, 0), 63);
        int gz = min(max(z0 - 1 + az, 0), 15);
        int gv = ((gh << 6) + gw) * 16 + gz;
        const float4* pk = (const float4*)(f_k + (size_t)gv * 64 + head * 8);
        ks4[sidx(i, 0)] = pk[0];
        ks4[sidx(i, 1)] = pk[1];
        const float4* pv = (const float4*)(f_v + (size_t)gv * 64 + head * 8);
        vs4[sidx(i, 0)] = pv[0];
        vs4[sidx(i, 1)] = pv[1];
    }
    if (tid < 125) bias_s[tid] = rpb[head * 125 + tid];
    __syncthreads();

    int lth = tid >> 5;
    int ltw = (tid >> 2) & 7;
    int ltz = tid & 3;
    int h = h0 + lth, w = w0 + ltw, z = z0 + ltz;
    int v = ((h << 6) + w) * 16 + z;

    const ulonglong2* pq = (const ulonglong2*)(f_q + (size_t)v * 64 + head * 8);
    ulonglong2 qa = pq[0], qb = pq[1];   // q pairs: (0,1)(2,3)(4,5)(6,7)

    int sh = min(max(h - 1, 0), 61);
    int sw = min(max(w - 1, 0), 61);
    int sz = min(max(z - 1, 0), 13);
    int lhh = sh - h0 + 1, lww = sw - w0 + 1, lzz = sz - z0 + 1;
    int rb = (sh - h + 2) * 25 + (sw - w + 2) * 5 + (sz - z + 2);

    float logits[27];
    int   hls[27];
    float mx = -1e30f;
#pragma unroll
    for (int a = 0; a < 3; a++)
#pragma unroll
    for (int b = 0; b < 3; b++)
#pragma unroll
    for (int cc = 0; cc < 3; cc++) {
        int m  = (a * 3 + b) * 3 + cc;
        int hl = ((lhh + a) * 10 + (lww + b)) * 6 + (lzz + cc);
        hls[m] = hl;
        ulonglong2 ka = *(const ulonglong2*)&ks4[sidx(hl, 0)];
        ulonglong2 kb = *(const ulonglong2*)&ks4[sidx(hl, 1)];
        u64 d2 = fmul2(qa.x, ka.x);
        d2 = ffma2(qa.y, ka.y, d2);
        d2 = ffma2(qb.x, kb.x, d2);
        d2 = ffma2(qb.y, kb.y, d2);
        float d = f2lo(d2) + f2hi(d2) + bias_s[rb + a * 25 + b * 5 + cc];
        logits[m] = d;
        mx = fmaxf(mx, d);
    }
    float ssum = 0.f;
#pragma unroll
    for (int m = 0; m < 27; m++) {
        float e = __expf(logits[m] - mx);
        logits[m] = e;
        ssum += e;
    }
    float inv = 1.0f / ssum;
    u64 o01 = 0, o23 = 0, o45 = 0, o67 = 0;   // 0x0 == (+0.f, +0.f)
#pragma unroll
    for (int m = 0; m < 27; m++) {
        u64 a2 = packdup(logits[m] * inv);
        ulonglong2 va = *(const ulonglong2*)&vs4[sidx(hls[m], 0)];
        ulonglong2 vb = *(const ulonglong2*)&vs4[sidx(hls[m], 1)];
        o01 = ffma2(a2, va.x, o01);
        o23 = ffma2(a2, va.y, o23);
        o45 = ffma2(a2, vb.x, o45);
        o67 = ffma2(a2, vb.y, o67);
    }
    int cb = head * 8;
    f_o[(size_t)(cb + 0) * NVOX + v] = f2lo(o01);
    f_o[(size_t)(cb + 1) * NVOX + v] = f2hi(o01);
    f_o[(size_t)(cb + 2) * NVOX + v] = f2lo(o23);
    f_o[(size_t)(cb + 3) * NVOX + v] = f2hi(o23);
    f_o[(size_t)(cb + 4) * NVOX + v] = f2lo(o45);
    f_o[(size_t)(cb + 5) * NVOX + v] = f2hi(o45);
    f_o[(size_t)(cb + 6) * NVOX + v] = f2lo(o67);
    f_o[(size_t)(cb + 7) * NVOX + v] = f2hi(o67);
}

// ---------------------------------------------------------------------------
extern "C" void kernel_launch(void* const* d_in, const int* in_sizes, int n_in,
                              void* d_out, int out_size) {
    const float* x    = (const float*)d_in[0];
    const float* skip = (const float*)d_in[1];
    const float* Wq   = (const float*)d_in[2];
    const float* bq   = (const float*)d_in[3];
    const float* Wk   = (const float*)d_in[4];
    const float* bk   = (const float*)d_in[5];
    const float* Wv   = (const float*)d_in[6];
    const float* bv   = (const float*)d_in[7];
    const float* Wo   = (const float*)d_in[8];
    const float* bo   = (const float*)d_in[9];
    const float* rpb  = (const float*)d_in[10];
    float* out = (float*)d_out;

    upsample_kernel<<<dim3(256, 8), 256>>>(x);
    stats_kernel<<<512, 256>>>(skip);
    fold_kernel<<<1, 64>>>(Wq, bq, Wk, bk, Wv, bv);
    proj_kernel<false><<<1024, 128>>>(0, skip, nullptr, nullptr, nullptr);  // q
    proj_kernel<false><<<1024, 128>>>(1, skip, nullptr, nullptr, nullptr);  // k
    proj_kernel<false><<<1024, 128>>>(2, skip, nullptr, nullptr, nullptr);  // v
    attn_kernel<<<dim3(256, 8), 256>>>(rpb);
    proj_kernel<true><<<1024, 128>>>(3, skip, Wo, bo, out);                 // o
}

// round 9
// speedup vs baseline: 1.0206x; 1.0206x over previous
#include <cuda_runtime.h>
#include <math.h>

#define NVOX 65536            // 64*64*16 voxels
#define CCH 64
#define NHEAD 8
#define DHEAD 8

typedef unsigned long long u64;

// ---------------- scratch (device globals; no allocation allowed) ----------
__device__ float f_xu[CCH * NVOX];   // upsampled x, channel-first [c][v]
__device__ float f_q[NVOX * CCH];    // q projection, voxel-major [v][c]
__device__ float f_k[NVOX * CCH];
__device__ float f_v[NVOX * CCH];
__device__ float f_o[CCH * NVOX];    // attention output, channel-first [c][v]
__device__ float g_psum[512], g_psumsq[512];   // [0:256] xu quarters, [256:512] skip quarters
__device__ float g_Wf[3][CCH * CCH];           // folded Wq, Wk, Wv
__device__ float g_bf[3][CCH];

// ---------------- helpers ---------------------------------------------------
__device__ __forceinline__ u64 ffma2(u64 a, u64 b, u64 c) {
    u64 d;
    asm("fma.rn.f32x2 %0, %1, %2, %3;" : "=l"(d) : "l"(a), "l"(b), "l"(c));
    return d;
}
__device__ __forceinline__ u64 fmul2(u64 a, u64 b) {
    u64 d;
    asm("mul.rn.f32x2 %0, %1, %2;" : "=l"(d) : "l"(a), "l"(b));
    return d;
}
__device__ __forceinline__ u64 packdup(float w) {
    unsigned u = __float_as_uint(w);
    return ((u64)u << 32) | (u64)u;
}
__device__ __forceinline__ float f2lo(u64 a) { return __uint_as_float((unsigned)a); }
__device__ __forceinline__ float f2hi(u64 a) { return __uint_as_float((unsigned)(a >> 32)); }

// ---------------- 1) trilinear upsample x(64,32,32,8) -> f_xu(64,64,64,16) --
__global__ __launch_bounds__(256) void upsample_kernel(const float* __restrict__ x) {
    int v = blockIdx.x * 256 + threadIdx.x;
    int h = v >> 10;
    int w = (v >> 4) & 63;
    int z = v & 15;

    const float rh = (float)(31.0 / 63.0);
    const float rw = (float)(31.0 / 63.0);
    const float rz = (float)(7.0 / 15.0);

    float ph = (float)h * rh; int ih = (int)ph; if (ih > 30) ih = 30; float fh = ph - (float)ih;
    float pw = (float)w * rw; int iw = (int)pw; if (iw > 30) iw = 30; float fw = pw - (float)iw;
    float pz = (float)z * rz; int iz = (int)pz; if (iz > 6)  iz = 6;  float fz = pz - (float)iz;

    int base = ih * 256 + iw * 8 + iz;   // strides: h=256, w=8, z=1
    int cbase = blockIdx.y * 8;

#pragma unroll
    for (int ci = 0; ci < 8; ci++) {
        int c = cbase + ci;
        const float* xc = x + c * 8192 + base;
        float c000 = xc[0],   c100 = xc[256], c010 = xc[8],   c110 = xc[264];
        float c001 = xc[1],   c101 = xc[257], c011 = xc[9],   c111 = xc[265];
        float a00 = c000 + fh * (c100 - c000);
        float a10 = c010 + fh * (c110 - c010);
        float a01 = c001 + fh * (c101 - c001);
        float a11 = c011 + fh * (c111 - c011);
        float b0  = a00 + fw * (a10 - a00);
        float b1  = a01 + fw * (a11 - a01);
        f_xu[c * NVOX + v] = b0 + fz * (b1 - b0);
    }
}

// ---------------- 2) per-channel partial sum / sumsq (xu and skip) ----------
__global__ __launch_bounds__(256) void stats_kernel(const float* __restrict__ skip) {
    int b = blockIdx.x;   // 0..511
    const int quart = NVOX / 4;
    const float* p;
    if (b < 256) p = f_xu + (b >> 2) * NVOX + (b & 3) * quart;
    else         p = skip + ((b - 256) >> 2) * NVOX + (b & 3) * quart;

    const float4* p4 = (const float4*)p;
    float s = 0.f, s2 = 0.f;
    for (int i = threadIdx.x; i < quart / 4; i += 256) {
        float4 val = p4[i];
        s  += val.x + val.y + val.z + val.w;
        s2 += val.x * val.x + val.y * val.y + val.z * val.z + val.w * val.w;
    }
    __shared__ float sh1[256], sh2[256];
    sh1[threadIdx.x] = s; sh2[threadIdx.x] = s2;
    __syncthreads();
    for (int off = 128; off > 0; off >>= 1) {
        if (threadIdx.x < off) {
            sh1[threadIdx.x] += sh1[threadIdx.x + off];
            sh2[threadIdx.x] += sh2[threadIdx.x + off];
        }
        __syncthreads();
    }
    if (threadIdx.x == 0) { g_psum[b] = sh1[0]; g_psumsq[b] = sh2[0]; }
}

// ---------------- 3) fold instance-norm (+ q scale) into weights -----------
__global__ void fold_kernel(const float* __restrict__ Wq, const float* __restrict__ bq,
                            const float* __restrict__ Wk, const float* __restrict__ bk,
                            const float* __restrict__ Wv, const float* __restrict__ bv) {
    __shared__ float skv[64], okv[64], sq_[64], oq_[64];
    int t = threadIdx.x;    // 64 threads
    const float invN = 1.0f / 65536.0f;
    float m  = (g_psum[4 * t] + g_psum[4 * t + 1] + g_psum[4 * t + 2] + g_psum[4 * t + 3]) * invN;
    float va = (g_psumsq[4 * t] + g_psumsq[4 * t + 1] + g_psumsq[4 * t + 2] + g_psumsq[4 * t + 3]) * invN - m * m;
    float sc = rsqrtf(va + 1e-5f);
    skv[t] = sc; okv[t] = -m * sc;
    m  = (g_psum[256 + 4 * t] + g_psum[257 + 4 * t] + g_psum[258 + 4 * t] + g_psum[259 + 4 * t]) * invN;
    va = (g_psumsq[256 + 4 * t] + g_psumsq[257 + 4 * t] + g_psumsq[258 + 4 * t] + g_psumsq[259 + 4 * t]) * invN - m * m;
    sc = rsqrtf(va + 1e-5f);
    sq_[t] = sc; oq_[t] = -m * sc;
    __syncthreads();

    const float scale = 0.3535533905932738f;  // dh^-0.5, dh=8
    float aq = 0.f, ak = 0.f, av = 0.f;
    for (int c = 0; c < 64; c++) {
        float wq = Wq[c * 64 + t]; g_Wf[0][c * 64 + t] = wq * sq_[c] * scale; aq += oq_[c] * wq;
        float wk = Wk[c * 64 + t]; g_Wf[1][c * 64 + t] = wk * skv[c];          ak += okv[c] * wk;
        float wv = Wv[c * 64 + t]; g_Wf[2][c * 64 + t] = wv * skv[c];          av += okv[c] * wv;
    }
    g_bf[0][t] = scale * (bq[t] + aq);
    g_bf[1][t] = bk[t] + ak;
    g_bf[2][t] = bv[t] + av;
}

// ---------------- 4) streaming projection ------------------------------------
// Block: 128 thr, 2 tiles of 64 voxels, og=tid>>4 (8 output groups of 8 ch),
// vg=tid&15 (4 voxels each). NPROJ=2 computes k and v from the same staged
// input. Tile t+1 is prefetched into registers while computing tile t, so only
// the first tile pays global latency. Dynamic smem (>48KB for NPROJ=2).
// sel: 0=q (skip->f_q), 1=kv (f_xu->f_k,f_v), 2=o (f_o->outext, channel-first)
#define PROJ_FMA16(P, I0, I1, I2, I3, WA, WB)                                   \
    {                                                                           \
        u64 w0 = (WA).x, w1 = (WA).y, w2 = (WB).x, w3 = (WB).y;                 \
        acc[P][0][0] = ffma2(I0, w0, acc[P][0][0]);                             \
        acc[P][0][1] = ffma2(I0, w1, acc[P][0][1]);                             \
        acc[P][0][2] = ffma2(I0, w2, acc[P][0][2]);                             \
        acc[P][0][3] = ffma2(I0, w3, acc[P][0][3]);                             \
        acc[P][1][0] = ffma2(I1, w0, acc[P][1][0]);                             \
        acc[P][1][1] = ffma2(I1, w1, acc[P][1][1]);                             \
        acc[P][1][2] = ffma2(I1, w2, acc[P][1][2]);                             \
        acc[P][1][3] = ffma2(I1, w3, acc[P][1][3]);                             \
        acc[P][2][0] = ffma2(I2, w0, acc[P][2][0]);                             \
        acc[P][2][1] = ffma2(I2, w1, acc[P][2][1]);                             \
        acc[P][2][2] = ffma2(I2, w2, acc[P][2][2]);                             \
        acc[P][2][3] = ffma2(I2, w3, acc[P][2][3]);                             \
        acc[P][3][0] = ffma2(I3, w0, acc[P][3][0]);                             \
        acc[P][3][1] = ffma2(I3, w1, acc[P][3][1]);                             \
        acc[P][3][2] = ffma2(I3, w2, acc[P][3][2]);                             \
        acc[P][3][3] = ffma2(I3, w3, acc[P][3][3]);                             \
    }

template <int NPROJ, bool CF_OUT>
__global__ __launch_bounds__(128) void proj_stream(int sel,
        const float* __restrict__ skip,
        const float* __restrict__ Wext, const float* __restrict__ bext,
        float* __restrict__ outext) {
    extern __shared__ char smem_raw[];
    u64*   sW   = (u64*)smem_raw;                         // [NPROJ][2048]
    u64*   sB   = sW + NPROJ * 2048;                      // [NPROJ][32]
    float* s_in = (float*)(sB + NPROJ * 32);              // [2][4096]

    const float* in;
    const float *W0, *b0, *W1 = nullptr, *b1 = nullptr;
    float *out0, *out1 = nullptr;
    if (sel == 0)      { in = skip; out0 = f_q; W0 = g_Wf[0]; b0 = g_bf[0]; }
    else if (sel == 1) { in = f_xu; out0 = f_k; out1 = f_v;
                         W0 = g_Wf[1]; b0 = g_bf[1]; W1 = g_Wf[2]; b1 = g_bf[2]; }
    else               { in = f_o;  out0 = outext; W0 = Wext; b0 = bext; }

    int tid = threadIdx.x;
    int vb0 = blockIdx.x * 128;

    for (int i = tid; i < 2048; i += 128) {
        sW[i] = ((const u64*)W0)[i];
        if (NPROJ == 2) sW[2048 + i] = ((const u64*)W1)[i];
    }
    if (tid < 32) {
        sB[tid] = ((const u64*)b0)[tid];
        if (NPROJ == 2) sB[32 + tid] = ((const u64*)b1)[tid];
    }
    // stage tile 0
    {
        int row = tid >> 4, col = (tid & 15) << 2;
#pragma unroll
        for (int j = 0; j < 8; j++) {
            *(float4*)&s_in[(row + j * 8) * 64 + col] =
                *(const float4*)(in + (size_t)(row + j * 8) * NVOX + vb0 + col);
        }
    }
    __syncthreads();

    int og = tid >> 4;     // 0..7
    int vg = tid & 15;     // 0..15
    int ldrow = tid >> 4, ldcol = (tid & 15) << 2;

#pragma unroll
    for (int t = 0; t < 2; t++) {
        int vb = vb0 + t * 64;
        const float* buf = s_in + (t & 1) * 4096;

        // prefetch tile 1 into registers while computing tile 0
        float4 pf[8];
        if (t == 0) {
#pragma unroll
            for (int j = 0; j < 8; j++)
                pf[j] = *(const float4*)(in + (size_t)(ldrow + j * 8) * NVOX + vb0 + 64 + ldcol);
        }

        u64 acc[NPROJ][4][4];
#pragma unroll
        for (int p = 0; p < NPROJ; p++)
#pragma unroll
            for (int v = 0; v < 4; v++)
#pragma unroll
                for (int op = 0; op < 4; op++) acc[p][v][op] = sB[p * 32 + og * 4 + op];

#pragma unroll 2
        for (int c = 0; c < 64; c++) {
            float4 iv = *(const float4*)&buf[c * 64 + vg * 4];
            u64 i0 = packdup(iv.x), i1 = packdup(iv.y), i2 = packdup(iv.z), i3 = packdup(iv.w);
            {
                ulonglong2 wa = *(const ulonglong2*)&sW[c * 32 + og * 4];
                ulonglong2 wb = *(const ulonglong2*)&sW[c * 32 + og * 4 + 2];
                PROJ_FMA16(0, i0, i1, i2, i3, wa, wb);
            }
            if (NPROJ == 2) {
                ulonglong2 wa = *(const ulonglong2*)&sW[2048 + c * 32 + og * 4];
                ulonglong2 wb = *(const ulonglong2*)&sW[2048 + c * 32 + og * 4 + 2];
                PROJ_FMA16(1, i0, i1, i2, i3, wa, wb);
            }
        }

        // store results for this tile
        if (!CF_OUT) {
#pragma unroll
            for (int p = 0; p < NPROJ; p++) {
                float* out = (p == 0) ? out0 : out1;
#pragma unroll
                for (int v = 0; v < 4; v++) {
                    size_t base = (size_t)(vb + vg * 4 + v) * 64 + og * 8;
                    ulonglong2 p0; p0.x = acc[p][v][0]; p0.y = acc[p][v][1];
                    ulonglong2 p1; p1.x = acc[p][v][2]; p1.y = acc[p][v][3];
                    *(ulonglong2*)(out + base)     = p0;
                    *(ulonglong2*)(out + base + 4) = p1;
                }
            }
        } else {
#pragma unroll
            for (int op = 0; op < 4; op++) {
                int ch = og * 8 + 2 * op;
                float4 lo = make_float4(f2lo(acc[0][0][op]), f2lo(acc[0][1][op]), f2lo(acc[0][2][op]), f2lo(acc[0][3][op]));
                float4 hi = make_float4(f2hi(acc[0][0][op]), f2hi(acc[0][1][op]), f2hi(acc[0][2][op]), f2hi(acc[0][3][op]));
                *(float4*)(out0 + (size_t)ch * NVOX + vb + vg * 4)       = lo;
                *(float4*)(out0 + (size_t)(ch + 1) * NVOX + vb + vg * 4) = hi;
            }
        }

        if (t == 0) {
            // commit prefetched tile 1 to the second buffer
#pragma unroll
            for (int j = 0; j < 8; j++)
                *(float4*)&s_in[4096 + (ldrow + j * 8) * 64 + ldcol] = pf[j];
            __syncthreads();
        }
    }
}

// ---------------- 5) tiled neighborhood attention (f32x2 packed) ------------
__device__ __forceinline__ int sidx(int hl, int j) {
    return (hl * 2 + j) ^ (((hl >> 2) & 3) << 1);
}

__global__ __launch_bounds__(256) void attn_kernel(const float* __restrict__ rpb) {
    __shared__ float4 ks4[1216];
    __shared__ float4 vs4[1216];
    __shared__ float bias_s[125];

    int tid  = threadIdx.x;
    int tb   = blockIdx.x;          // 0..255 : 8x8x4 tiles
    int head = blockIdx.y;
    int h0 = (tb >> 5) * 8;
    int w0 = ((tb >> 2) & 7) * 8;
    int z0 = (tb & 3) * 4;

    for (int i = tid; i < 600; i += 256) {
        int ah = i / 60; int r = i - ah * 60; int aw = r / 6; int az = r - aw * 6;
        int gh = min(max(h0 - 1 + ah, 0), 63);
        int gw = min(max(w0 - 1 + aw, 0), 63);
        int gz = min(max(z0 - 1 + az, 0), 15);
        int gv = ((gh << 6) + gw) * 16 + gz;
        const float4* pk = (const float4*)(f_k + (size_t)gv * 64 + head * 8);
        ks4[sidx(i, 0)] = pk[0];
        ks4[sidx(i, 1)] = pk[1];
        const float4* pv = (const float4*)(f_v + (size_t)gv * 64 + head * 8);
        vs4[sidx(i, 0)] = pv[0];
        vs4[sidx(i, 1)] = pv[1];
    }
    if (tid < 125) bias_s[tid] = rpb[head * 125 + tid];
    __syncthreads();

    int lth = tid >> 5;
    int ltw = (tid >> 2) & 7;
    int ltz = tid & 3;
    int h = h0 + lth, w = w0 + ltw, z = z0 + ltz;
    int v = ((h << 6) + w) * 16 + z;

    const ulonglong2* pq = (const ulonglong2*)(f_q + (size_t)v * 64 + head * 8);
    ulonglong2 qa = pq[0], qb = pq[1];   // q pairs: (0,1)(2,3)(4,5)(6,7)

    int sh = min(max(h - 1, 0), 61);
    int sw = min(max(w - 1, 0), 61);
    int sz = min(max(z - 1, 0), 13);
    int lhh = sh - h0 + 1, lww = sw - w0 + 1, lzz = sz - z0 + 1;
    int rb = (sh - h + 2) * 25 + (sw - w + 2) * 5 + (sz - z + 2);

    float logits[27];
    int   hls[27];
    float mx = -1e30f;
#pragma unroll
    for (int a = 0; a < 3; a++)
#pragma unroll
    for (int b = 0; b < 3; b++)
#pragma unroll
    for (int cc = 0; cc < 3; cc++) {
        int m  = (a * 3 + b) * 3 + cc;
        int hl = ((lhh + a) * 10 + (lww + b)) * 6 + (lzz + cc);
        hls[m] = hl;
        ulonglong2 ka = *(const ulonglong2*)&ks4[sidx(hl, 0)];
        ulonglong2 kb = *(const ulonglong2*)&ks4[sidx(hl, 1)];
        u64 d2 = fmul2(qa.x, ka.x);
        d2 = ffma2(qa.y, ka.y, d2);
        d2 = ffma2(qb.x, kb.x, d2);
        d2 = ffma2(qb.y, kb.y, d2);
        float d = f2lo(d2) + f2hi(d2) + bias_s[rb + a * 25 + b * 5 + cc];
        logits[m] = d;
        mx = fmaxf(mx, d);
    }
    float ssum = 0.f;
#pragma unroll
    for (int m = 0; m < 27; m++) {
        float e = __expf(logits[m] - mx);
        logits[m] = e;
        ssum += e;
    }
    float inv = 1.0f / ssum;
    u64 o01 = 0, o23 = 0, o45 = 0, o67 = 0;   // 0x0 == (+0.f, +0.f)
#pragma unroll
    for (int m = 0; m < 27; m++) {
        u64 a2 = packdup(logits[m] * inv);
        ulonglong2 va = *(const ulonglong2*)&vs4[sidx(hls[m], 0)];
        ulonglong2 vb = *(const ulonglong2*)&vs4[sidx(hls[m], 1)];
        o01 = ffma2(a2, va.x, o01);
        o23 = ffma2(a2, va.y, o23);
        o45 = ffma2(a2, vb.x, o45);
        o67 = ffma2(a2, vb.y, o67);
    }
    int cb = head * 8;
    f_o[(size_t)(cb + 0) * NVOX + v] = f2lo(o01);
    f_o[(size_t)(cb + 1) * NVOX + v] = f2hi(o01);
    f_o[(size_t)(cb + 2) * NVOX + v] = f2lo(o23);
    f_o[(size_t)(cb + 3) * NVOX + v] = f2hi(o23);
    f_o[(size_t)(cb + 4) * NVOX + v] = f2lo(o45);
    f_o[(size_t)(cb + 5) * NVOX + v] = f2hi(o45);
    f_o[(size_t)(cb + 6) * NVOX + v] = f2lo(o67);
    f_o[(size_t)(cb + 7) * NVOX + v] = f2hi(o67);
}

// ---------------------------------------------------------------------------
extern "C" void kernel_launch(void* const* d_in, const int* in_sizes, int n_in,
                              void* d_out, int out_size) {
    const float* x    = (const float*)d_in[0];
    const float* skip = (const float*)d_in[1];
    const float* Wq   = (const float*)d_in[2];
    const float* bq   = (const float*)d_in[3];
    const float* Wk   = (const float*)d_in[4];
    const float* bk   = (const float*)d_in[5];
    const float* Wv   = (const float*)d_in[6];
    const float* bv   = (const float*)d_in[7];
    const float* Wo   = (const float*)d_in[8];
    const float* bo   = (const float*)d_in[9];
    const float* rpb  = (const float*)d_in[10];
    float* out = (float*)d_out;

    const int SMEM1 = (2048 + 32) * 8 + 2 * 4096 * 4;   // 49408 B
    const int SMEM2 = 2 * (2048 + 32) * 8 + 2 * 4096 * 4; // 66048 B
    cudaFuncSetAttribute(proj_stream<1, false>, cudaFuncAttributeMaxDynamicSharedMemorySize, SMEM1);
    cudaFuncSetAttribute(proj_stream<2, false>, cudaFuncAttributeMaxDynamicSharedMemorySize, SMEM2);
    cudaFuncSetAttribute(proj_stream<1, true>,  cudaFuncAttributeMaxDynamicSharedMemorySize, SMEM1);

    upsample_kernel<<<dim3(256, 8), 256>>>(x);
    stats_kernel<<<512, 256>>>(skip);
    fold_kernel<<<1, 64>>>(Wq, bq, Wk, bk, Wv, bv);
    proj_stream<1, false><<<512, 128, SMEM1>>>(0, skip, nullptr, nullptr, nullptr);  // q
    proj_stream<2, false><<<512, 128, SMEM2>>>(1, skip, nullptr, nullptr, nullptr);  // k+v
    attn_kernel<<<dim3(256, 8), 256>>>(rpb);
    proj_stream<1, true><<<512, 128, SMEM1>>>(2, skip, Wo, bo, out);                 // o
}